// round 8
// baseline (speedup 1.0000x reference)
#include <cuda_runtime.h>

#define K       512
#define THREADS 256
#define T8      1038
#define NN8     256

#define BUF_ELEMS 16842752
__device__ float g_bufA[BUF_ELEMS];
__device__ float g_bufB[BUF_ELEMS];

#define DECL_FILTERS \
    constexpr float LO[16] = { \
         0.0018899503327594609f, -0.0003029205147213668f, -0.01495225833704823f, \
         0.003808752013890615f,   0.049137179673607506f,  -0.027219029917056003f, \
        -0.05194583810770904f,    0.3644418948353314f,     0.7771857517005235f, \
         0.4813596512583722f,    -0.061273359067658524f,  -0.1432942383508097f, \
         0.007607487324917605f,   0.03169508781149298f,   -0.0005421323317911481f, \
        -0.0033824159510061256f }; \
    constexpr float HI[16] = { \
        -0.0033824159510061256f,  0.0005421323317911481f,  0.03169508781149298f, \
        -0.007607487324917605f,  -0.1432942383508097f,     0.061273359067658524f, \
         0.4813596512583722f,    -0.7771857517005235f,     0.3644418948353314f, \
         0.05194583810770904f,   -0.027219029917056003f,  -0.049137179673607506f, \
         0.003808752013890615f,   0.01495225833704823f,   -0.0003029205147213668f, \
        -0.0018899503327594609f };

// Classic interleaved conv (boundary fallback): w[2q+i] taps.
template<int Q>
__device__ __forceinline__ void convN(const float* w, float* lo, float* hi) {
    DECL_FILTERS
    #pragma unroll
    for (int q = 0; q < Q; q++) {
        float a = 0.f, b = 0.f;
        #pragma unroll
        for (int i = 0; i < 16; i++) {
            float v = w[2 * q + i];
            a = fmaf(v, LO[i], a);
            b = fmaf(v, HI[i], b);
        }
        lo[q] = a; hi[q] = b;
    }
}

// Deinterleaved conv: output q uses we[OFF+q+j], wo[OFF+q+j], j=0..7.
template<int Q, int OFF>
__device__ __forceinline__ void convDI(const float* we, const float* wo, float* lo, float* hi) {
    DECL_FILTERS
    #pragma unroll
    for (int q = 0; q < Q; q++) {
        float a = 0.f, b = 0.f;
        #pragma unroll
        for (int j = 0; j < 8; j++) {
            float ve = we[OFF + q + j];
            float vo = wo[OFF + q + j];
            a = fmaf(ve, LO[2*j], a);  a = fmaf(vo, LO[2*j+1], a);
            b = fmaf(ve, HI[2*j], b);  b = fmaf(vo, HI[2*j+1], b);
        }
        lo[q] = a; hi[q] = b;
    }
}

// 12 floats from 16B-aligned smem (3x LDS.128, conflict-free: 16B lane stride).
__device__ __forceinline__ void ld12(const float* s, float* w) {
    float4 a = *(const float4*)s;
    float4 b = *(const float4*)(s + 4);
    float4 c = *(const float4*)(s + 8);
    w[0]=a.x; w[1]=a.y; w[2]=a.z; w[3]=a.w;
    w[4]=b.x; w[5]=b.y; w[6]=b.z; w[7]=b.w;
    w[8]=c.x; w[9]=c.y; w[10]=c.z; w[11]=c.w;
}

__device__ __forceinline__ int igray(int j) { j ^= j >> 1; j ^= j >> 2; j ^= j >> 4; return j; }

// ---------------- Mid kernel: two fused DWT levels, deinterleaved smem ----------------
// sp: se[p]=x[aa+2p-8] (p>=4), so[p]=x[aa+2p-7].  aL/aH: e[p]=A[ms+2p-8], o[p]=A[ms+2p-7].
__global__ void __launch_bounds__(THREADS)
dwt_pair_mid(const float* __restrict__ ext_in, int in_sel, int out_sel, int lev,
             int t_in, int stride_in, int t_outA, int t_outB, int stride_out)
{
    __shared__ float sp[2 * 1056];
    __shared__ float aL[2 * 528];
    __shared__ float aH[2 * 528];

    const float* in  = (in_sel == 0) ? ext_in : ((in_sel == 1) ? g_bufA : g_bufB);
    float*       outb = (out_sel == 1) ? g_bufA : g_bufB;

    int row = blockIdx.y;
    int k0  = blockIdx.x * K;
    const float* src = in + (size_t)row * stride_in;

    int mstart = 2 * k0 - 14;           if (mstart < 0) mstart = 0;
    int mend   = 2 * k0 + 2 * K - 1;    if (mend > t_outA - 1) mend = t_outA - 1;
    int aa = 2 * mstart - 16;
    int D  = mend - mstart;
    bool bint = (2 * k0 - 14 >= 0) && (2 * (k0 + K - 1) + 1 <= t_outA - 1);

    // ---- input window: deinterleave even/odd ----
    if (bint && aa >= 0 && aa + 2092 <= t_in) {
        const float4* g = (const float4*)(src + aa);       // aa = 4k0-44, aligned
        for (int q = threadIdx.x; q < 523; q += THREADS) {
            float4 v = g[q];
            *(float2*)(sp + 2*q + 4)        = make_float2(v.x, v.z);
            *(float2*)(sp + 1056 + 2*q + 4) = make_float2(v.y, v.w);
        }
    } else {
        int nload = 2 * D + 18;
        for (int w = threadIdx.x; w < nload; w += THREADS) {
            int m = aa + w;
            if (m < 0)      m = -m;
            if (m >= t_in)  m = 2 * t_in - 2 - m;
            sp[(w & 1) * 1056 + (w >> 1) + 4] = src[m];
        }
    }
    __syncthreads();

    // ---- level A (uniform fast path; reflect was materialized at load) ----
    for (int ml0 = 4 * threadIdx.x; ml0 <= D; ml0 += 4 * THREADS) {
        float we[12], wo[12];
        ld12(sp + ml0 + 4, we);            // taps at [1..11]
        ld12(sp + 1056 + ml0 + 4, wo);
        float lo[4], hi[4];
        convDI<4, 1>(we, wo, lo, hi);
        int cnt = D - ml0 + 1; if (cnt > 4) cnt = 4;
        if (cnt == 4) {
            *(float2*)(aL + (ml0 >> 1) + 4)       = make_float2(lo[0], lo[2]);
            *(float2*)(aL + 528 + (ml0 >> 1) + 4) = make_float2(lo[1], lo[3]);
            *(float2*)(aH + (ml0 >> 1) + 4)       = make_float2(hi[0], hi[2]);
            *(float2*)(aH + 528 + (ml0 >> 1) + 4) = make_float2(hi[1], hi[3]);
        } else {
            for (int q = 0; q < cnt; q++) {
                int ml = ml0 + q;
                aL[(ml & 1) * 528 + (ml >> 1) + 4] = lo[q];
                aH[(ml & 1) * 528 + (ml >> 1) + 4] = hi[q];
            }
        }
    }
    __syncthreads();

    // ---- level B ----
    int c  = threadIdx.x >> 7;
    int s  = threadIdx.x & 127;
    int kk = k0 + 4 * s;
    if (kk >= t_outB) return;

    const float* A = c ? aH : aL;
    float lo2[4], hi2[4];
    if (bint) {
        float we[12], wo[12];
        ld12(A + 4 * s + 4, we);           // taps at [0..10]
        ld12(A + 528 + 4 * s + 4, wo);
        convDI<4, 0>(we, wo, lo2, hi2);
    } else {
        float wf[22];
        #pragma unroll
        for (int i = 0; i < 22; i++) {
            int f = 2 * kk - 14 + i;
            if (f < 0)        f = -f;
            if (f >= t_outA)  f = 2 * t_outA - 2 - f;
            int a = f - mstart;
            wf[i] = A[(a & 1) * 528 + (a >> 1) + 4];
        }
        convN<4>(wf, lo2, hi2);
    }

    int b    = row >> lev;
    int node = row & ((1 << lev) - 1);
    size_t r = ((size_t)((b << (lev + 2)) + 4 * node + 2 * c)) * stride_out + kk;
    if (kk + 4 <= t_outB) {
        *(float4*)(outb + r)              = make_float4(lo2[0], lo2[1], lo2[2], lo2[3]);
        *(float4*)(outb + r + stride_out) = make_float4(hi2[0], hi2[1], hi2[2], hi2[3]);
    } else {
        for (int q = 0; q < t_outB - kk; q++) {
            outb[r + q]              = lo2[q];
            outb[r + stride_out + q] = hi2[q];
        }
    }
}

// ---------------- Final kernel: whole L6 row -> L8 + permute/log/sign ----------------
// sp: se[p]=x[2p-8], so[p]=x[2p-7].  aL/aH: e[p]=A[2p-8], o[p]=A[2p-7].
__global__ void __launch_bounds__(THREADS)
dwt_final_row(float* __restrict__ out)
{
    __shared__ float sp[2 * 2064];
    __shared__ float aL[2 * 1040];
    __shared__ float aH[2 * 1040];

    int row = blockIdx.x;                       // 0..4095
    const float* src = g_bufA + (size_t)row * 4112;

    {
        const float4* g4 = (const float4*)src;  // stride 4112 -> aligned, padded
        for (int q = threadIdx.x; q < 1028; q += THREADS) {
            float4 v = g4[q];
            *(float2*)(sp + 2*q + 4)        = make_float2(v.x, v.z);
            *(float2*)(sp + 2064 + 2*q + 4) = make_float2(v.y, v.w);
        }
    }
    __syncthreads();

    // ---- level A: 4110 -> 2062 ----
    for (int m0 = 4 * threadIdx.x; m0 < 2062; m0 += 4 * THREADS) {
        int cnt = 2062 - m0; if (cnt > 4) cnt = 4;
        float lo[4], hi[4];
        if (m0 >= 8 && m0 <= 2048) {
            float we[12], wo[12];
            ld12(sp + m0 - 4, we);             // taps at [1..11]
            ld12(sp + 2064 + m0 - 4, wo);
            convDI<4, 1>(we, wo, lo, hi);
        } else {
            float wf[22];
            #pragma unroll
            for (int i = 0; i < 22; i++) {
                int f = 2 * m0 - 14 + i;
                if (f < 0)     f = -f;
                if (f >= 4110) f = 8218 - f;
                wf[i] = sp[(f & 1) * 2064 + (f >> 1) + 4];
            }
            convN<4>(wf, lo, hi);
        }
        if (cnt == 4) {
            *(float2*)(aL + (m0 >> 1) + 4)        = make_float2(lo[0], lo[2]);
            *(float2*)(aL + 1040 + (m0 >> 1) + 4) = make_float2(lo[1], lo[3]);
            *(float2*)(aH + (m0 >> 1) + 4)        = make_float2(hi[0], hi[2]);
            *(float2*)(aH + 1040 + (m0 >> 1) + 4) = make_float2(hi[1], hi[3]);
        } else {
            for (int q = 0; q < cnt; q++) {
                int m = m0 + q;
                aL[(m & 1) * 1040 + (m >> 1) + 4] = lo[q];
                aH[(m & 1) * 1040 + (m >> 1) + 4] = hi[q];
            }
        }
    }
    __syncthreads();

    // ---- level B: 2062 -> 1038, fused permute/log/sign ----
    int c = threadIdx.x >> 7;
    int s = threadIdx.x & 127;
    const float* A = c ? aH : aL;

    int b    = row >> 6;
    int node = row & 63;
    int p0 = igray(4 * node + 2 * c);
    int p1 = igray(4 * node + 2 * c + 1);
    size_t ob = (size_t)b * (2 * NN8 * T8);
    const size_t SOFF = (size_t)NN8 * T8;
    float* L0 = out + ob + (size_t)p0 * T8;
    float* L1 = out + ob + (size_t)p1 * T8;

    for (int k0 = 4 * s; k0 < T8; k0 += 512) {
        int cnt = T8 - k0; if (cnt > 4) cnt = 4;
        float lo2[4], hi2[4];
        if (k0 >= 8 && k0 <= 1024) {
            float we[12], wo[12];
            ld12(A + k0 - 4, we);              // taps at [1..11]
            ld12(A + 1040 + k0 - 4, wo);
            convDI<4, 1>(we, wo, lo2, hi2);
        } else {
            float wf[22];
            #pragma unroll
            for (int i = 0; i < 22; i++) {
                int f = 2 * k0 - 14 + i;
                if (f < 0)     f = -f;
                if (f >= 2062) f = 4122 - f;
                wf[i] = A[(f & 1) * 1040 + (f >> 1) + 4];
            }
            convN<4>(wf, lo2, hi2);
        }

        if (cnt == 4) {
            *(float2*)(L0 + k0)     = make_float2(__logf(fmaf(lo2[0], lo2[0], 1e-12f)),
                                                  __logf(fmaf(lo2[1], lo2[1], 1e-12f)));
            *(float2*)(L0 + k0 + 2) = make_float2(__logf(fmaf(lo2[2], lo2[2], 1e-12f)),
                                                  __logf(fmaf(lo2[3], lo2[3], 1e-12f)));
            *(float2*)(L0 + SOFF + k0)     = make_float2(lo2[0] < 0.f ? -1.f : 1.f,
                                                         lo2[1] < 0.f ? -1.f : 1.f);
            *(float2*)(L0 + SOFF + k0 + 2) = make_float2(lo2[2] < 0.f ? -1.f : 1.f,
                                                         lo2[3] < 0.f ? -1.f : 1.f);
            *(float2*)(L1 + k0)     = make_float2(__logf(fmaf(hi2[0], hi2[0], 1e-12f)),
                                                  __logf(fmaf(hi2[1], hi2[1], 1e-12f)));
            *(float2*)(L1 + k0 + 2) = make_float2(__logf(fmaf(hi2[2], hi2[2], 1e-12f)),
                                                  __logf(fmaf(hi2[3], hi2[3], 1e-12f)));
            *(float2*)(L1 + SOFF + k0)     = make_float2(hi2[0] < 0.f ? -1.f : 1.f,
                                                         hi2[1] < 0.f ? -1.f : 1.f);
            *(float2*)(L1 + SOFF + k0 + 2) = make_float2(hi2[2] < 0.f ? -1.f : 1.f,
                                                         hi2[3] < 0.f ? -1.f : 1.f);
        } else {
            for (int q = 0; q < cnt; q++) {
                float x = lo2[q], y = hi2[q];
                L0[k0 + q]        = __logf(fmaf(x, x, 1e-12f));
                L0[SOFF + k0 + q] = (x < 0.f) ? -1.f : 1.f;
                L1[k0 + q]        = __logf(fmaf(y, y, 1e-12f));
                L1[SOFF + k0 + q] = (y < 0.f) ? -1.f : 1.f;
            }
        }
    }
}

extern "C" void kernel_launch(void* const* d_in, const int* in_sizes, int n_in_args,
                              void* d_out, int out_size) {
    (void)in_sizes; (void)n_in_args; (void)out_size;
    const float* in0 = (const float*)d_in[0];
    float* out = (float*)d_out;

    // t chain: 262144 -> 131079 -> 65547 -> 32781 -> 16398 -> 8206 -> 4110 -> 2062 -> 1038
    dim3 g0((65547 + K - 1) / K, 64);      // ext -> L2 (bufA)
    dwt_pair_mid<<<g0, THREADS>>>(in0, 0, 1, 0, 262144, 262144, 131079, 65547, 65548);
    dim3 g1((16398 + K - 1) / K, 256);     // L2 -> L4 (bufB)
    dwt_pair_mid<<<g1, THREADS>>>(in0, 1, 2, 2, 65547, 65548, 32781, 16398, 16400);
    dim3 g2((4110 + K - 1) / K, 1024);     // L4 -> L6 (bufA)
    dwt_pair_mid<<<g2, THREADS>>>(in0, 2, 1, 4, 16398, 16400, 8206, 4110, 4112);
    // L6 -> L8 + permute/log/sign, one block per L6 row
    dwt_final_row<<<4096, THREADS>>>(out);
}

// round 9
// speedup vs baseline: 1.0012x; 1.0012x over previous
#include <cuda_runtime.h>

typedef unsigned long long ull;

#define K       512
#define THREADS 256
#define KA      4
#define T8      1038
#define NN8     256

#define BUF_ELEMS 16842752
__device__ float g_bufA[BUF_ELEMS];
__device__ float g_bufB[BUF_ELEMS];

#define DECL_FILTERS \
    constexpr float LO[16] = { \
         0.0018899503327594609f, -0.0003029205147213668f, -0.01495225833704823f, \
         0.003808752013890615f,   0.049137179673607506f,  -0.027219029917056003f, \
        -0.05194583810770904f,    0.3644418948353314f,     0.7771857517005235f, \
         0.4813596512583722f,    -0.061273359067658524f,  -0.1432942383508097f, \
         0.007607487324917605f,   0.03169508781149298f,   -0.0005421323317911481f, \
        -0.0033824159510061256f }; \
    constexpr float HI[16] = { \
        -0.0033824159510061256f,  0.0005421323317911481f,  0.03169508781149298f, \
        -0.007607487324917605f,  -0.1432942383508097f,     0.061273359067658524f, \
         0.4813596512583722f,    -0.7771857517005235f,     0.3644418948353314f, \
         0.05194583810770904f,   -0.027219029917056003f,  -0.049137179673607506f, \
         0.003808752013890615f,   0.01495225833704823f,   -0.0003029205147213668f, \
        -0.0018899503327594609f };

// ---- packed f32x2 helpers ----
__device__ __forceinline__ ull ffma2(ull a, ull v, ull c) {
    asm("fma.rn.f32x2 %0, %1, %2, %0;" : "+l"(a) : "l"(v), "l"(c));
    return a;
}
__device__ __forceinline__ float hsum(ull u) {
    float x, y;
    asm("mov.b64 {%0,%1}, %2;" : "=f"(x), "=f"(y) : "l"(u));
    return x + y;
}
__device__ __forceinline__ ull cpk(float x, float y) {
    return (ull)__float_as_uint(x) | ((ull)__float_as_uint(y) << 32);
}

// Load 22-float window (11 ull pairs) from smem, base float index ≡ 0 mod 4.
__device__ __forceinline__ void ldw_a0(const float* s, ull* u) {
    #pragma unroll
    for (int i = 0; i < 5; i++) {
        ulonglong2 t = *(const ulonglong2*)(s + 4 * i);
        u[2*i] = t.x; u[2*i+1] = t.y;
    }
    u[10] = *(const ull*)(s + 20);
}
// Same, base float index ≡ 2 mod 4 (8B aligned; s+2 is 16B aligned).
__device__ __forceinline__ void ldw_a2(const float* s, ull* u) {
    u[0] = *(const ull*)s;
    #pragma unroll
    for (int i = 0; i < 5; i++) {
        ulonglong2 t = *(const ulonglong2*)(s + 2 + 4 * i);
        u[2*i+1] = t.x; u[2*i+2] = t.y;
    }
}

// Packed conv: u[j] = {w[2j], w[2j+1]}; output q uses pairs u[q+j], j=0..7.
template<int Q>
__device__ __forceinline__ void convP(const ull* u, float* lo, float* hi) {
    DECL_FILTERS
    #pragma unroll
    for (int q = 0; q < Q; q++) {
        ull a = 0ULL;
        #pragma unroll
        for (int j = 0; j < 8; j++) a = ffma2(a, u[q + j], cpk(LO[2*j], LO[2*j+1]));
        lo[q] = hsum(a);
    }
    #pragma unroll
    for (int q = 0; q < Q; q++) {
        ull a = 0ULL;
        #pragma unroll
        for (int j = 0; j < 8; j++) a = ffma2(a, u[q + j], cpk(HI[2*j], HI[2*j+1]));
        hi[q] = hsum(a);
    }
}

// Scalar fallback conv (boundary paths): taps w[2q+i].
template<int Q>
__device__ __forceinline__ void convN(const float* w, float* lo, float* hi) {
    DECL_FILTERS
    #pragma unroll
    for (int q = 0; q < Q; q++) {
        float a = 0.f, b = 0.f;
        #pragma unroll
        for (int i = 0; i < 16; i++) {
            float v = w[2 * q + i];
            a = fmaf(v, LO[i], a);
            b = fmaf(v, HI[i], b);
        }
        lo[q] = a; hi[q] = b;
    }
}

__device__ __forceinline__ int igray(int j) { j ^= j >> 1; j ^= j >> 2; j ^= j >> 4; return j; }

// ---------------- Mid kernel: two fused DWT levels ----------------
__global__ void __launch_bounds__(THREADS)
dwt_pair_mid(const float* __restrict__ ext_in, int in_sel, int out_sel, int lev,
             int t_in, int stride_in, int t_outA, int t_outB, int stride_out)
{
    __shared__ __align__(16) float s_in[2104];
    __shared__ __align__(16) float s_lo[1040];
    __shared__ __align__(16) float s_hi[1040];

    const float* in  = (in_sel == 0) ? ext_in : ((in_sel == 1) ? g_bufA : g_bufB);
    float*       outb = (out_sel == 1) ? g_bufA : g_bufB;

    int row = blockIdx.y;
    int k0  = blockIdx.x * K;
    const float* src = in + (size_t)row * stride_in;

    int mstart = 2 * k0 - 14;           if (mstart < 0) mstart = 0;
    int mend   = 2 * k0 + 2 * K - 1;    if (mend > t_outA - 1) mend = t_outA - 1;
    int aa = 2 * mstart - 16;
    bool bint = (2 * k0 - 14 >= 0) && (2 * (k0 + K - 1) + 1 <= t_outA - 1);

    // ---- input window ----
    if (bint && aa >= 0 && aa + 2092 <= t_in) {
        const float4* g  = (const float4*)(src + aa);   // aa = 4k0-44, 16B aligned
        float4*       s4 = (float4*)s_in;
        #pragma unroll
        for (int q = threadIdx.x; q < 523; q += THREADS) s4[q] = g[q];
    } else {
        int nload = 2 * (mend - mstart) + 18;
        for (int idx = threadIdx.x; idx < nload; idx += THREADS) {
            int m = aa + idx;
            if (m < 0)      m = -m;
            if (m >= t_in)  m = 2 * t_in - 2 - m;
            s_in[idx] = src[m];
        }
    }
    __syncthreads();

    // ---- level A: packed conv (reflect already materialized at load) ----
    for (int m0 = mstart + KA * threadIdx.x; m0 <= mend; m0 += KA * THREADS) {
        ull u[11];
        ldw_a2(s_in + 2 * (m0 - mstart) + 2, u);        // base = 8t+2 (mod 4 == 2)
        float lo[KA], hi[KA];
        convP<KA>(u, lo, hi);
        int cnt = mend - m0 + 1; if (cnt > KA) cnt = KA;
        int d = m0 - mstart;                            // multiple of 4
        if (cnt == KA) {
            *(float4*)(s_lo + d) = make_float4(lo[0], lo[1], lo[2], lo[3]);
            *(float4*)(s_hi + d) = make_float4(hi[0], hi[1], hi[2], hi[3]);
        } else {
            for (int q = 0; q < cnt; q++) { s_lo[d + q] = lo[q]; s_hi[d + q] = hi[q]; }
        }
    }
    __syncthreads();

    // ---- level B ----
    int c  = threadIdx.x >> 7;
    int s  = threadIdx.x & 127;
    int kk = k0 + 4 * s;
    if (kk >= t_outB) return;

    const float* A = c ? s_hi : s_lo;
    float lo2[4], hi2[4];
    if (bint) {
        ull u[11];
        ldw_a0(A + 8 * s, u);                           // base = 8s (mod 4 == 0)
        convP<4>(u, lo2, hi2);
    } else {
        float wf[22];
        #pragma unroll
        for (int i = 0; i < 22; i++) {
            int f = 2 * kk - 14 + i;
            if (f < 0)        f = -f;
            if (f >= t_outA)  f = 2 * t_outA - 2 - f;
            wf[i] = A[f - mstart];
        }
        convN<4>(wf, lo2, hi2);
    }

    int b    = row >> lev;
    int node = row & ((1 << lev) - 1);
    size_t r = ((size_t)((b << (lev + 2)) + 4 * node + 2 * c)) * stride_out + kk;
    if (kk + 4 <= t_outB) {
        *(float4*)(outb + r)              = make_float4(lo2[0], lo2[1], lo2[2], lo2[3]);
        *(float4*)(outb + r + stride_out) = make_float4(hi2[0], hi2[1], hi2[2], hi2[3]);
    } else {
        for (int q = 0; q < t_outB - kk; q++) {
            outb[r + q]              = lo2[q];
            outb[r + stride_out + q] = hi2[q];
        }
    }
}

// ---------------- Final kernel: whole L6 row -> L8 + permute/log/sign ----------------
__global__ void __launch_bounds__(THREADS)
dwt_final_row(float* __restrict__ out)
{
    __shared__ __align__(16) float s_in[4112];
    __shared__ __align__(16) float s_lo[2064];
    __shared__ __align__(16) float s_hi[2064];

    int row = blockIdx.x;                       // 0..4095
    const float* src = g_bufA + (size_t)row * 4112;

    {
        const float4* g4 = (const float4*)src;
        float4* s4 = (float4*)s_in;
        #pragma unroll
        for (int q = threadIdx.x; q < 1028; q += THREADS) s4[q] = g4[q];
    }
    __syncthreads();

    // ---- level A: 4110 -> 2062 ----
    for (int m0 = 4 * threadIdx.x; m0 < 2062; m0 += 4 * THREADS) {
        int cnt = 2062 - m0; if (cnt > 4) cnt = 4;
        int jb = 2 * m0 - 14;
        float lo[4], hi[4];
        if (m0 >= 8 && m0 <= 2048) {
            ull u[11];
            ldw_a2(s_in + jb, u);               // jb = 8t-14 (mod 4 == 2)
            convP<4>(u, lo, hi);
        } else {
            float wf[22];
            #pragma unroll
            for (int i = 0; i < 22; i++) {
                int f = jb + i;
                if (f < 0)     f = -f;
                if (f >= 4110) f = 8218 - f;
                wf[i] = s_in[f];
            }
            convN<4>(wf, lo, hi);
        }
        if (cnt == 4) {
            *(float4*)(s_lo + m0) = make_float4(lo[0], lo[1], lo[2], lo[3]);
            *(float4*)(s_hi + m0) = make_float4(hi[0], hi[1], hi[2], hi[3]);
        } else {
            for (int q = 0; q < cnt; q++) { s_lo[m0 + q] = lo[q]; s_hi[m0 + q] = hi[q]; }
        }
    }
    __syncthreads();

    // ---- level B: 2062 -> 1038, fused permute/log/sign ----
    int c = threadIdx.x >> 7;
    int s = threadIdx.x & 127;
    const float* A = c ? s_hi : s_lo;

    int b    = row >> 6;
    int node = row & 63;
    int p0 = igray(4 * node + 2 * c);
    int p1 = igray(4 * node + 2 * c + 1);
    size_t ob = (size_t)b * (2 * NN8 * T8);
    const size_t SOFF = (size_t)NN8 * T8;
    float* L0 = out + ob + (size_t)p0 * T8;
    float* L1 = out + ob + (size_t)p1 * T8;

    for (int k0 = 4 * s; k0 < T8; k0 += 512) {
        int cnt = T8 - k0; if (cnt > 4) cnt = 4;
        int jb = 2 * k0 - 14;
        float lo2[4], hi2[4];
        if (k0 >= 8 && k0 <= 1024) {
            ull u[11];
            ldw_a2(A + jb, u);                  // jb = 8s-14 (mod 4 == 2)
            convP<4>(u, lo2, hi2);
        } else {
            float wf[22];
            #pragma unroll
            for (int i = 0; i < 22; i++) {
                int f = jb + i;
                if (f < 0)     f = -f;
                if (f >= 2062) f = 4122 - f;
                wf[i] = A[f];
            }
            convN<4>(wf, lo2, hi2);
        }

        if (cnt == 4) {
            *(float2*)(L0 + k0)     = make_float2(__logf(fmaf(lo2[0], lo2[0], 1e-12f)),
                                                  __logf(fmaf(lo2[1], lo2[1], 1e-12f)));
            *(float2*)(L0 + k0 + 2) = make_float2(__logf(fmaf(lo2[2], lo2[2], 1e-12f)),
                                                  __logf(fmaf(lo2[3], lo2[3], 1e-12f)));
            *(float2*)(L0 + SOFF + k0)     = make_float2(lo2[0] < 0.f ? -1.f : 1.f,
                                                         lo2[1] < 0.f ? -1.f : 1.f);
            *(float2*)(L0 + SOFF + k0 + 2) = make_float2(lo2[2] < 0.f ? -1.f : 1.f,
                                                         lo2[3] < 0.f ? -1.f : 1.f);
            *(float2*)(L1 + k0)     = make_float2(__logf(fmaf(hi2[0], hi2[0], 1e-12f)),
                                                  __logf(fmaf(hi2[1], hi2[1], 1e-12f)));
            *(float2*)(L1 + k0 + 2) = make_float2(__logf(fmaf(hi2[2], hi2[2], 1e-12f)),
                                                  __logf(fmaf(hi2[3], hi2[3], 1e-12f)));
            *(float2*)(L1 + SOFF + k0)     = make_float2(hi2[0] < 0.f ? -1.f : 1.f,
                                                         hi2[1] < 0.f ? -1.f : 1.f);
            *(float2*)(L1 + SOFF + k0 + 2) = make_float2(hi2[2] < 0.f ? -1.f : 1.f,
                                                         hi2[3] < 0.f ? -1.f : 1.f);
        } else {
            for (int q = 0; q < cnt; q++) {
                float x = lo2[q], y = hi2[q];
                L0[k0 + q]        = __logf(fmaf(x, x, 1e-12f));
                L0[SOFF + k0 + q] = (x < 0.f) ? -1.f : 1.f;
                L1[k0 + q]        = __logf(fmaf(y, y, 1e-12f));
                L1[SOFF + k0 + q] = (y < 0.f) ? -1.f : 1.f;
            }
        }
    }
}

extern "C" void kernel_launch(void* const* d_in, const int* in_sizes, int n_in_args,
                              void* d_out, int out_size) {
    (void)in_sizes; (void)n_in_args; (void)out_size;
    const float* in0 = (const float*)d_in[0];
    float* out = (float*)d_out;

    // t chain: 262144 -> 131079 -> 65547 -> 32781 -> 16398 -> 8206 -> 4110 -> 2062 -> 1038
    dim3 g0((65547 + K - 1) / K, 64);      // ext -> L2 (bufA)
    dwt_pair_mid<<<g0, THREADS>>>(in0, 0, 1, 0, 262144, 262144, 131079, 65547, 65548);
    dim3 g1((16398 + K - 1) / K, 256);     // L2 -> L4 (bufB)
    dwt_pair_mid<<<g1, THREADS>>>(in0, 1, 2, 2, 65547, 65548, 32781, 16398, 16400);
    dim3 g2((4110 + K - 1) / K, 1024);     // L4 -> L6 (bufA)
    dwt_pair_mid<<<g2, THREADS>>>(in0, 2, 1, 4, 16398, 16400, 8206, 4110, 4112);
    // L6 -> L8 + permute/log/sign, one block per L6 row
    dwt_final_row<<<4096, THREADS>>>(out);
}

// round 10
// speedup vs baseline: 1.0094x; 1.0082x over previous
#include <cuda_runtime.h>

#define THREADS 256
#define KC      256          // level-C outputs per block per output row
#define T8      1038
#define NN8     256

#define BUF_ELEMS 16842752
__device__ float g_bufA[BUF_ELEMS];   // L3: 512 rows x 32784 = 16,785,408
__device__ float g_bufB[BUF_ELEMS];   // L6: 4096 rows x 4112 = 16,842,752

#define DECL_FILTERS \
    constexpr float LO[16] = { \
         0.0018899503327594609f, -0.0003029205147213668f, -0.01495225833704823f, \
         0.003808752013890615f,   0.049137179673607506f,  -0.027219029917056003f, \
        -0.05194583810770904f,    0.3644418948353314f,     0.7771857517005235f, \
         0.4813596512583722f,    -0.061273359067658524f,  -0.1432942383508097f, \
         0.007607487324917605f,   0.03169508781149298f,   -0.0005421323317911481f, \
        -0.0033824159510061256f }; \
    constexpr float HI[16] = { \
        -0.0033824159510061256f,  0.0005421323317911481f,  0.03169508781149298f, \
        -0.007607487324917605f,  -0.1432942383508097f,     0.061273359067658524f, \
         0.4813596512583722f,    -0.7771857517005235f,     0.3644418948353314f, \
         0.05194583810770904f,   -0.027219029917056003f,  -0.049137179673607506f, \
         0.003808752013890615f,   0.01495225833704823f,   -0.0003029205147213668f, \
        -0.0018899503327594609f };

// Interleaved conv: taps w[2q+i].
template<int Q>
__device__ __forceinline__ void convN(const float* w, float* lo, float* hi) {
    DECL_FILTERS
    #pragma unroll
    for (int q = 0; q < Q; q++) {
        float a = 0.f, b = 0.f;
        #pragma unroll
        for (int i = 0; i < 16; i++) {
            float v = w[2 * q + i];
            a = fmaf(v, LO[i], a);
            b = fmaf(v, HI[i], b);
        }
        lo[q] = a; hi[q] = b;
    }
}

// 22-float window, base 16B-aligned: w[i] = s[i].
__device__ __forceinline__ void ldwin0(const float* s, float* w) {
    float4 wv[6];
    const float4* p = (const float4*)s;
    #pragma unroll
    for (int i = 0; i < 6; i++) wv[i] = p[i];
    const float* f = (const float*)wv;
    #pragma unroll
    for (int i = 0; i < 22; i++) w[i] = f[i];
}
// 22-float window, base ≡ 2 mod 4 floats (s-2 is 16B-aligned): w[i] = s[i].
__device__ __forceinline__ void ldwin2(const float* s, float* w) {
    float4 wv[6];
    const float4* p = (const float4*)(s - 2);
    #pragma unroll
    for (int i = 0; i < 6; i++) wv[i] = p[i];
    const float* f = (const float*)wv;
    #pragma unroll
    for (int i = 0; i < 22; i++) w[i] = f[i + 2];
}

__device__ __forceinline__ int igray(int j) { j ^= j >> 1; j ^= j >> 2; j ^= j >> 4; return j; }

// ---------------- Tri kernel: three fused DWT levels ----------------
// Input rows at level `lev`, length t_in. Produces level lev+3 rows.
__global__ void __launch_bounds__(THREADS)
dwt_tri(const float* __restrict__ ext_in, int in_sel, int out_sel, int lev,
        int t_in, int stride_in, int tA, int tB, int tC, int stride_out)
{
    __shared__ __align__(16) float s_in[2160];
    __shared__ __align__(16) float aLo[1080];
    __shared__ __align__(16) float aHi[1080];
    __shared__ __align__(16) float sB[4][544];

    const float* in  = (in_sel == 0) ? ext_in : ((in_sel == 1) ? g_bufA : g_bufB);
    float*       outb = (out_sel == 1) ? g_bufA : g_bufB;

    int row = blockIdx.y;
    int kC  = blockIdx.x * KC;
    int tid = threadIdx.x;
    const float* src = in + (size_t)row * stride_in;

    int mBs = 2 * kC - 14;            if (mBs < 0) mBs = 0;
    int mBe = 2 * kC + 2 * KC - 1;    if (mBe > tB - 1) mBe = tB - 1;
    int mAs = 2 * mBs - 14;           if (mAs < 0) mAs = 0;
    int mAe = 2 * mBe + 1;            if (mAe > tA - 1) mAe = tA - 1;
    int aa  = 2 * mAs - 14;           // raw first tap position
    int a2  = aa - 2;                 // load origin (16B aligned when interior)
    bool bint = (2 * kC - 14 >= 0) && (2 * kC + 2 * KC - 1 <= tB - 1)
             && (4 * kC - 42 >= 0) && (2 * (2 * kC + 2 * KC - 1) + 1 <= tA - 1)
             && (a2 >= 0) && (a2 + 2160 <= t_in);

    // ---- input window: s_in[idx] = x[reflect(a2 + idx)] ----
    if (bint) {
        const float4* g  = (const float4*)(src + a2);
        float4*       s4 = (float4*)s_in;
        #pragma unroll
        for (int q = tid; q < 540; q += THREADS) s4[q] = g[q];
    } else {
        int nload = 2 * mAe + 4 - aa;
        for (int idx = tid; idx < nload; idx += THREADS) {
            int m = a2 + idx;
            if (m < 0)      m = -m;
            if (m >= t_in)  m = 2 * t_in - 2 - m;
            s_in[idx] = src[m];
        }
    }
    __syncthreads();

    // ---- level A: positions [mAs, mAe] (reflect already materialized) ----
    for (int m0 = mAs + 4 * tid; m0 <= mAe; m0 += 4 * THREADS) {
        int u4 = m0 - mAs;                     // multiple of 4
        float w[22];
        ldwin2(s_in + 2 * u4 + 2, w);          // base = 2*u4+2 (≡2 mod 4)
        float lo[4], hi[4];
        convN<4>(w, lo, hi);
        int cnt = mAe - m0 + 1; if (cnt > 4) cnt = 4;
        if (cnt == 4) {
            *(float4*)(aLo + u4) = make_float4(lo[0], lo[1], lo[2], lo[3]);
            *(float4*)(aHi + u4) = make_float4(hi[0], hi[1], hi[2], hi[3]);
        } else {
            for (int q = 0; q < cnt; q++) { aLo[u4 + q] = lo[q]; aHi[u4 + q] = hi[q]; }
        }
    }
    __syncthreads();

    // ---- level B: 2 rows x [mBs, mBe] ----
    {
        int r = tid >> 7;
        int s = tid & 127;
        const float* A = r ? aHi : aLo;
        for (int d = 4 * s; d <= mBe - mBs; d += 512) {
            float w[22];
            if (bint) {
                ldwin0(A + 2 * d, w);          // base 2d ≡ 0 mod 8
            } else {
                #pragma unroll
                for (int i = 0; i < 22; i++) {
                    int f = 2 * (mBs + d) - 14 + i;
                    if (f < 0)     f = -f;
                    if (f >= tA)   f = 2 * tA - 2 - f;
                    w[i] = A[f - mAs];
                }
            }
            float lo[4], hi[4];
            convN<4>(w, lo, hi);
            int cnt = mBe - mBs - d + 1; if (cnt > 4) cnt = 4;
            if (cnt == 4) {
                *(float4*)(sB[2 * r]     + d) = make_float4(lo[0], lo[1], lo[2], lo[3]);
                *(float4*)(sB[2 * r + 1] + d) = make_float4(hi[0], hi[1], hi[2], hi[3]);
            } else {
                for (int q = 0; q < cnt; q++) {
                    sB[2 * r][d + q]     = lo[q];
                    sB[2 * r + 1][d + q] = hi[q];
                }
            }
        }
    }
    __syncthreads();

    // ---- level C: 4 B-rows -> 8 output rows, write gmem ----
    {
        int rc = tid >> 6;                     // 0..3
        int sc = tid & 63;
        int kk = kC + 4 * sc;
        if (kk <= tC - 1) {
            const float* Bx = sB[rc];
            float w[22];
            if (bint) {
                ldwin0(Bx + 8 * sc, w);        // base 8*sc
            } else {
                #pragma unroll
                for (int i = 0; i < 22; i++) {
                    int f = 2 * kk - 14 + i;
                    if (f < 0)    f = -f;
                    if (f >= tB)  f = 2 * tB - 2 - f;
                    w[i] = Bx[f - mBs];
                }
            }
            float lo[4], hi[4];
            convN<4>(w, lo, hi);

            int node = row & ((1 << lev) - 1);
            int b    = row >> lev;
            int obase = (b << (lev + 3)) + (node << 3) + 2 * rc;
            size_t rr = (size_t)obase * stride_out + kk;
            int cnt = tC - kk; if (cnt > 4) cnt = 4;
            if (cnt == 4) {
                *(float4*)(outb + rr)              = make_float4(lo[0], lo[1], lo[2], lo[3]);
                *(float4*)(outb + rr + stride_out) = make_float4(hi[0], hi[1], hi[2], hi[3]);
            } else {
                for (int q = 0; q < cnt; q++) {
                    outb[rr + q]              = lo[q];
                    outb[rr + stride_out + q] = hi[q];
                }
            }
        }
    }
}

// ---------------- Final kernel: whole L6 row -> L8 + permute/log/sign ----------------
__global__ void __launch_bounds__(THREADS)
dwt_final_row(float* __restrict__ out)
{
    __shared__ __align__(16) float s_in[4112];
    __shared__ __align__(16) float s_lo[2064];
    __shared__ __align__(16) float s_hi[2064];

    int row = blockIdx.x;                       // 0..4095
    const float* src = g_bufB + (size_t)row * 4112;

    {
        const float4* g4 = (const float4*)src;
        float4* s4 = (float4*)s_in;
        #pragma unroll
        for (int q = threadIdx.x; q < 1028; q += THREADS) s4[q] = g4[q];
    }
    __syncthreads();

    // ---- level A: 4110 -> 2062 ----
    for (int m0 = 4 * threadIdx.x; m0 < 2062; m0 += 4 * THREADS) {
        int cnt = 2062 - m0; if (cnt > 4) cnt = 4;
        int jb = 2 * m0 - 14;
        float lo[4], hi[4];
        float w[22];
        if (m0 >= 8 && m0 <= 2048) {
            ldwin2(s_in + jb, w);               // jb ≡ 2 mod 4
        } else {
            #pragma unroll
            for (int i = 0; i < 22; i++) {
                int f = jb + i;
                if (f < 0)     f = -f;
                if (f >= 4110) f = 8218 - f;
                w[i] = s_in[f];
            }
        }
        convN<4>(w, lo, hi);
        if (cnt == 4) {
            *(float4*)(s_lo + m0) = make_float4(lo[0], lo[1], lo[2], lo[3]);
            *(float4*)(s_hi + m0) = make_float4(hi[0], hi[1], hi[2], hi[3]);
        } else {
            for (int q = 0; q < cnt; q++) { s_lo[m0 + q] = lo[q]; s_hi[m0 + q] = hi[q]; }
        }
    }
    __syncthreads();

    // ---- level B: 2062 -> 1038, fused permute/log/sign ----
    int c = threadIdx.x >> 7;
    int s = threadIdx.x & 127;
    const float* A = c ? s_hi : s_lo;

    int b    = row >> 6;
    int node = row & 63;
    int p0 = igray(4 * node + 2 * c);
    int p1 = igray(4 * node + 2 * c + 1);
    size_t ob = (size_t)b * (2 * NN8 * T8);
    const size_t SOFF = (size_t)NN8 * T8;
    float* L0 = out + ob + (size_t)p0 * T8;
    float* L1 = out + ob + (size_t)p1 * T8;

    for (int k0 = 4 * s; k0 < T8; k0 += 512) {
        int cnt = T8 - k0; if (cnt > 4) cnt = 4;
        int jb = 2 * k0 - 14;
        float lo2[4], hi2[4];
        float w[22];
        if (k0 >= 8 && k0 <= 1024) {
            ldwin2(A + jb, w);
        } else {
            #pragma unroll
            for (int i = 0; i < 22; i++) {
                int f = jb + i;
                if (f < 0)     f = -f;
                if (f >= 2062) f = 4122 - f;
                w[i] = A[f];
            }
        }
        convN<4>(w, lo2, hi2);

        if (cnt == 4) {
            *(float2*)(L0 + k0)     = make_float2(__logf(fmaf(lo2[0], lo2[0], 1e-12f)),
                                                  __logf(fmaf(lo2[1], lo2[1], 1e-12f)));
            *(float2*)(L0 + k0 + 2) = make_float2(__logf(fmaf(lo2[2], lo2[2], 1e-12f)),
                                                  __logf(fmaf(lo2[3], lo2[3], 1e-12f)));
            *(float2*)(L0 + SOFF + k0)     = make_float2(lo2[0] < 0.f ? -1.f : 1.f,
                                                         lo2[1] < 0.f ? -1.f : 1.f);
            *(float2*)(L0 + SOFF + k0 + 2) = make_float2(lo2[2] < 0.f ? -1.f : 1.f,
                                                         lo2[3] < 0.f ? -1.f : 1.f);
            *(float2*)(L1 + k0)     = make_float2(__logf(fmaf(hi2[0], hi2[0], 1e-12f)),
                                                  __logf(fmaf(hi2[1], hi2[1], 1e-12f)));
            *(float2*)(L1 + k0 + 2) = make_float2(__logf(fmaf(hi2[2], hi2[2], 1e-12f)),
                                                  __logf(fmaf(hi2[3], hi2[3], 1e-12f)));
            *(float2*)(L1 + SOFF + k0)     = make_float2(hi2[0] < 0.f ? -1.f : 1.f,
                                                         hi2[1] < 0.f ? -1.f : 1.f);
            *(float2*)(L1 + SOFF + k0 + 2) = make_float2(hi2[2] < 0.f ? -1.f : 1.f,
                                                         hi2[3] < 0.f ? -1.f : 1.f);
        } else {
            for (int q = 0; q < cnt; q++) {
                float x = lo2[q], y = hi2[q];
                L0[k0 + q]        = __logf(fmaf(x, x, 1e-12f));
                L0[SOFF + k0 + q] = (x < 0.f) ? -1.f : 1.f;
                L1[k0 + q]        = __logf(fmaf(y, y, 1e-12f));
                L1[SOFF + k0 + q] = (y < 0.f) ? -1.f : 1.f;
            }
        }
    }
}

extern "C" void kernel_launch(void* const* d_in, const int* in_sizes, int n_in_args,
                              void* d_out, int out_size) {
    (void)in_sizes; (void)n_in_args; (void)out_size;
    const float* in0 = (const float*)d_in[0];
    float* out = (float*)d_out;

    // t chain: 262144 ->L1 131079 ->L2 65547 ->L3 32781 ->L4 16398 ->L5 8206
    //          ->L6 4110 ->L7 2062 ->L8 1038
    // K1: ext (64 rows, 262144) -> L3 (512 rows, 32781; stride 32784) in bufA
    dim3 g1((32781 + KC - 1) / KC, 64);
    dwt_tri<<<g1, THREADS>>>(in0, 0, 1, 0, 262144, 262144, 131079, 65547, 32781, 32784);
    // K2: L3 -> L6 (4096 rows, 4110; stride 4112) in bufB
    dim3 g2((4110 + KC - 1) / KC, 512);
    dwt_tri<<<g2, THREADS>>>(in0, 1, 2, 3, 32781, 32784, 16398, 8206, 4110, 4112);
    // K3: L6 -> L8 + permute/log/sign
    dwt_final_row<<<4096, THREADS>>>(out);
}

// round 11
// speedup vs baseline: 1.0955x; 1.0853x over previous
#include <cuda_runtime.h>

#define K       512
#define THREADS 256
#define KA      4
#define T8      1038
#define NN8     256

#define BUF_ELEMS 16842752
__device__ float g_bufA[BUF_ELEMS];   // L2: 256 rows x 65548
__device__ float g_bufB[BUF_ELEMS];   // L4: 1024 rows x 16400

#define DECL_FILTERS \
    constexpr float LO[16] = { \
         0.0018899503327594609f, -0.0003029205147213668f, -0.01495225833704823f, \
         0.003808752013890615f,   0.049137179673607506f,  -0.027219029917056003f, \
        -0.05194583810770904f,    0.3644418948353314f,     0.7771857517005235f, \
         0.4813596512583722f,    -0.061273359067658524f,  -0.1432942383508097f, \
         0.007607487324917605f,   0.03169508781149298f,   -0.0005421323317911481f, \
        -0.0033824159510061256f }; \
    constexpr float HI[16] = { \
        -0.0033824159510061256f,  0.0005421323317911481f,  0.03169508781149298f, \
        -0.007607487324917605f,  -0.1432942383508097f,     0.061273359067658524f, \
         0.4813596512583722f,    -0.7771857517005235f,     0.3644418948353314f, \
         0.05194583810770904f,   -0.027219029917056003f,  -0.049137179673607506f, \
         0.003808752013890615f,   0.01495225833704823f,   -0.0003029205147213668f, \
        -0.0018899503327594609f };

template<int Q>
__device__ __forceinline__ void convN(const float* w, float* lo, float* hi) {
    DECL_FILTERS
    #pragma unroll
    for (int q = 0; q < Q; q++) {
        float a = 0.f, b = 0.f;
        #pragma unroll
        for (int i = 0; i < 16; i++) {
            float v = w[2 * q + i];
            a = fmaf(v, LO[i], a);
            b = fmaf(v, HI[i], b);
        }
        lo[q] = a; hi[q] = b;
    }
}

// 22-float window, base index ≡ 2 mod 4 (s-2 is 16B-aligned): w[i] = s[i].
__device__ __forceinline__ void ldwin2(const float* s, float* w) {
    float4 wv[6];
    const float4* p = (const float4*)(s - 2);
    #pragma unroll
    for (int i = 0; i < 6; i++) wv[i] = p[i];
    const float* f = (const float*)wv;
    #pragma unroll
    for (int i = 0; i < 22; i++) w[i] = f[i + 2];
}
// 22-float window, 16B-aligned base.
__device__ __forceinline__ void ldwin0(const float* s, float* w) {
    float4 wv[6];
    const float4* p = (const float4*)s;
    #pragma unroll
    for (int i = 0; i < 6; i++) wv[i] = p[i];
    const float* f = (const float*)wv;
    #pragma unroll
    for (int i = 0; i < 22; i++) w[i] = f[i];
}

__device__ __forceinline__ int igray(int j) { j ^= j >> 1; j ^= j >> 2; j ^= j >> 4; return j; }

// ---------------- Mid kernel (unchanged from R7) ----------------
__global__ void __launch_bounds__(THREADS)
dwt_pair_mid(const float* __restrict__ ext_in, int in_sel, int out_sel, int lev,
             int t_in, int stride_in, int t_outA, int t_outB, int stride_out)
{
    __shared__ __align__(16) float s_in[2104];
    __shared__ __align__(16) float s_lo[1040];
    __shared__ __align__(16) float s_hi[1040];

    const float* in  = (in_sel == 0) ? ext_in : ((in_sel == 1) ? g_bufA : g_bufB);
    float*       outb = (out_sel == 1) ? g_bufA : g_bufB;

    int row = blockIdx.y;
    int k0  = blockIdx.x * K;
    const float* src = in + (size_t)row * stride_in;

    int mstart = 2 * k0 - 14;           if (mstart < 0) mstart = 0;
    int mend   = 2 * k0 + 2 * K - 1;    if (mend > t_outA - 1) mend = t_outA - 1;
    int aa = 2 * mstart - 16;
    bool bint = (2 * k0 - 14 >= 0) && (2 * (k0 + K - 1) + 1 <= t_outA - 1);

    if (bint && aa >= 0 && aa + 2092 <= t_in) {
        const float4* g  = (const float4*)(src + aa);
        float4*       s4 = (float4*)s_in;
        #pragma unroll
        for (int q = threadIdx.x; q < 523; q += THREADS) s4[q] = g[q];
    } else {
        int nload = 2 * (mend - mstart) + 18;
        for (int idx = threadIdx.x; idx < nload; idx += THREADS) {
            int m = aa + idx;
            if (m < 0)      m = -m;
            if (m >= t_in)  m = 2 * t_in - 2 - m;
            s_in[idx] = src[m];
        }
    }
    __syncthreads();

    for (int m0 = mstart + KA * threadIdx.x; m0 <= mend; m0 += KA * THREADS) {
        float w[22];
        ldwin2(s_in + 2 * (m0 - mstart) + 2, w);
        float lo[KA], hi[KA];
        convN<KA>(w, lo, hi);
        int cnt = mend - m0 + 1; if (cnt > KA) cnt = KA;
        int d = m0 - mstart;
        if (cnt == KA) {
            *(float4*)(s_lo + d) = make_float4(lo[0], lo[1], lo[2], lo[3]);
            *(float4*)(s_hi + d) = make_float4(hi[0], hi[1], hi[2], hi[3]);
        } else {
            for (int q = 0; q < cnt; q++) { s_lo[d + q] = lo[q]; s_hi[d + q] = hi[q]; }
        }
    }
    __syncthreads();

    int c  = threadIdx.x >> 7;
    int s  = threadIdx.x & 127;
    int kk = k0 + 4 * s;
    if (kk >= t_outB) return;

    const float* A = c ? s_hi : s_lo;
    float lo2[4], hi2[4];
    if (bint) {
        float w[22];
        ldwin0(A + 8 * s, w);
        convN<4>(w, lo2, hi2);
    } else {
        float wf[22];
        #pragma unroll
        for (int i = 0; i < 22; i++) {
            int f = 2 * kk - 14 + i;
            if (f < 0)        f = -f;
            if (f >= t_outA)  f = 2 * t_outA - 2 - f;
            wf[i] = A[f - mstart];
        }
        convN<4>(wf, lo2, hi2);
    }

    int b    = row >> lev;
    int node = row & ((1 << lev) - 1);
    size_t r = ((size_t)((b << (lev + 2)) + 4 * node + 2 * c)) * stride_out + kk;
    if (kk + 4 <= t_outB) {
        *(float4*)(outb + r)              = make_float4(lo2[0], lo2[1], lo2[2], lo2[3]);
        *(float4*)(outb + r + stride_out) = make_float4(hi2[0], hi2[1], hi2[2], hi2[3]);
    } else {
        for (int q = 0; q < t_outB - kk; q++) {
            outb[r + q]              = lo2[q];
            outb[r + stride_out + q] = hi2[q];
        }
    }
}

// ---------------- Quad kernel: L4 -> L8 + permute/log/sign ----------------
// Stored layout per level: logical position p at index (p - origin), origin = Os-16
// (x uses origin gx). Mirror extensions written at boundaries so all convs are
// uniform aligned fast-path.
#define STR_A 2248
#define STR_B 1140
#define STR_C 584
#define P1OFF 4560     // P0 = [0,4560), P1 = [4560, 9232)

template<int NR>
__device__ __forceinline__ void quad_pass(const float* __restrict__ inR, int inOrigin,
                                          int inStride, float* __restrict__ outR,
                                          int outStride, int Os, int Oe, int t_out,
                                          int tid)
{
    constexpr int TPR = 256 / NR;
    int r = tid / TPR;
    int s = tid % TPR;
    const float* inRow = inR + r * inStride;
    float* oLo = outR + (2 * r) * outStride;
    float* oHi = outR + (2 * r + 1) * outStride;
    int outOrigin = Os - 16;
    bool cb = (Os == 0);
    bool ct = (Oe == t_out - 1);

    for (int m0 = Os + 4 * s; m0 <= Oe; m0 += 4 * TPR) {
        float w[22];
        ldwin2(inRow + (2 * m0 - 14 - inOrigin), w);
        float lo[4], hi[4];
        convN<4>(w, lo, hi);
        int d = m0 - outOrigin;                 // multiple of 4
        if (m0 + 3 <= Oe) {
            *(float4*)(oLo + d) = make_float4(lo[0], lo[1], lo[2], lo[3]);
            *(float4*)(oHi + d) = make_float4(hi[0], hi[1], hi[2], hi[3]);
        } else {
            for (int q = 0; q <= Oe - m0; q++) { oLo[d + q] = lo[q]; oHi[d + q] = hi[q]; }
        }
        if (cb && m0 <= 14) {
            #pragma unroll
            for (int q = 0; q < 4; q++) {
                int p = m0 + q;
                if (p >= 1 && p <= 14) { oLo[16 - p] = lo[q]; oHi[16 - p] = hi[q]; }
            }
        }
        if (ct && m0 + 3 >= t_out - 21) {
            #pragma unroll
            for (int q = 0; q < 4; q++) {
                int p = m0 + q;
                if (p >= t_out - 21 && p <= t_out - 2 && p <= Oe) {
                    int slot = 2 * (t_out - 1) - p - outOrigin;
                    oLo[slot] = lo[q]; oHi[slot] = hi[q];
                }
            }
        }
    }
}

__global__ void __launch_bounds__(THREADS)
dwt_quad(float* __restrict__ out)
{
    __shared__ __align__(16) float smem[9232];

    const int t4 = 16398, t5 = 8206, t6 = 4110, t7 = 2062, t8 = 1038;
    int r   = blockIdx.y;                 // L4 row 0..1023
    int j   = blockIdx.x;                 // tile 0..3
    int tid = threadIdx.x;

    int Ds = 264 * j;
    int De = min(Ds + 263, t8 - 1);
    int Cs = 2 * Ds - 14; if (Cs < 0) Cs = 0; Cs &= ~3;
    int Ce = min(t7 - 1, 2 * De + 1);
    int Bs = 2 * Cs - 14; if (Bs < 0) Bs = 0; Bs &= ~3;
    int Be = min(t6 - 1, 2 * Ce + 1);
    int As = 2 * Bs - 14; if (As < 0) As = 0; As &= ~3;
    int Ae = min(t5 - 1, 2 * Be + 1);
    int gx = 2 * As - 16;
    int xlen = 2 * Ae + 22 - gx;

    float* sx = smem;
    float* sA = smem + P1OFF;
    float* sB = smem;
    float* sC = smem + P1OFF;

    // ---- stage x (L4 row) with reflect materialized ----
    {
        const float* src = g_bufB + (size_t)r * 16400;
        int nv = (xlen + 3) >> 2;
        if (gx >= 0 && gx + 4 * nv <= t4) {
            const float4* g4 = (const float4*)(src + gx);
            float4* s4 = (float4*)sx;
            for (int q = tid; q < nv; q += THREADS) s4[q] = g4[q];
        } else {
            for (int idx = tid; idx < xlen; idx += THREADS) {
                int m = gx + idx;
                if (m < 0)     m = -m;
                if (m >= t4)   m = 2 * t4 - 2 - m;
                sx[idx] = src[m];
            }
        }
    }
    __syncthreads();

    quad_pass<1>(sx, gx, 0, sA, STR_A, As, Ae, t5, tid);          // L5
    __syncthreads();
    quad_pass<2>(sA, As - 16, STR_A, sB, STR_B, Bs, Be, t6, tid); // L6
    __syncthreads();
    quad_pass<4>(sB, Bs - 16, STR_B, sC, STR_C, Cs, Ce, t7, tid); // L7
    __syncthreads();

    // ---- L8 + permute/log/sign ----
    int rc = tid >> 5;                    // C row 0..7
    int sc = tid & 31;
    const float* Crow = sC + rc * STR_C;
    int b    = r >> 4;
    int n4   = r & 15;
    int p0 = igray(n4 * 16 + 2 * rc);
    int p1 = igray(n4 * 16 + 2 * rc + 1);
    size_t ob = (size_t)b * (2 * NN8 * T8);
    const size_t SOFF = (size_t)NN8 * T8;
    float* L0 = out + ob + (size_t)p0 * T8;
    float* L1 = out + ob + (size_t)p1 * T8;

    for (int kk = Ds + 4 * sc; kk <= De; kk += 128) {
        float w[22];
        ldwin2(Crow + (2 * kk + 2 - Cs), w);
        float lo[4], hi[4];
        convN<4>(w, lo, hi);
        if (kk + 3 <= De) {
            *(float2*)(L0 + kk)     = make_float2(__logf(fmaf(lo[0], lo[0], 1e-12f)),
                                                  __logf(fmaf(lo[1], lo[1], 1e-12f)));
            *(float2*)(L0 + kk + 2) = make_float2(__logf(fmaf(lo[2], lo[2], 1e-12f)),
                                                  __logf(fmaf(lo[3], lo[3], 1e-12f)));
            *(float2*)(L0 + SOFF + kk)     = make_float2(lo[0] < 0.f ? -1.f : 1.f,
                                                         lo[1] < 0.f ? -1.f : 1.f);
            *(float2*)(L0 + SOFF + kk + 2) = make_float2(lo[2] < 0.f ? -1.f : 1.f,
                                                         lo[3] < 0.f ? -1.f : 1.f);
            *(float2*)(L1 + kk)     = make_float2(__logf(fmaf(hi[0], hi[0], 1e-12f)),
                                                  __logf(fmaf(hi[1], hi[1], 1e-12f)));
            *(float2*)(L1 + kk + 2) = make_float2(__logf(fmaf(hi[2], hi[2], 1e-12f)),
                                                  __logf(fmaf(hi[3], hi[3], 1e-12f)));
            *(float2*)(L1 + SOFF + kk)     = make_float2(hi[0] < 0.f ? -1.f : 1.f,
                                                         hi[1] < 0.f ? -1.f : 1.f);
            *(float2*)(L1 + SOFF + kk + 2) = make_float2(hi[2] < 0.f ? -1.f : 1.f,
                                                         hi[3] < 0.f ? -1.f : 1.f);
        } else {
            for (int q = 0; q <= De - kk; q++) {
                float x = lo[q], y = hi[q];
                L0[kk + q]        = __logf(fmaf(x, x, 1e-12f));
                L0[SOFF + kk + q] = (x < 0.f) ? -1.f : 1.f;
                L1[kk + q]        = __logf(fmaf(y, y, 1e-12f));
                L1[SOFF + kk + q] = (y < 0.f) ? -1.f : 1.f;
            }
        }
    }
}

extern "C" void kernel_launch(void* const* d_in, const int* in_sizes, int n_in_args,
                              void* d_out, int out_size) {
    (void)in_sizes; (void)n_in_args; (void)out_size;
    const float* in0 = (const float*)d_in[0];
    float* out = (float*)d_out;

    // t chain: 262144 -> 131079 -> 65547 -> 32781 -> 16398 -> 8206 -> 4110 -> 2062 -> 1038
    dim3 g0((65547 + K - 1) / K, 64);      // ext -> L2 (bufA, stride 65548)
    dwt_pair_mid<<<g0, THREADS>>>(in0, 0, 1, 0, 262144, 262144, 131079, 65547, 65548);
    dim3 g1((16398 + K - 1) / K, 256);     // L2 -> L4 (bufB, stride 16400)
    dwt_pair_mid<<<g1, THREADS>>>(in0, 1, 2, 2, 65547, 65548, 32781, 16398, 16400);
    // L4 -> L8 + permute/log/sign: 4 tiles x 1024 L4 rows
    dwt_quad<<<dim3(4, 1024), THREADS>>>(out);
}